// round 4
// baseline (speedup 1.0000x reference)
#include <cuda_runtime.h>
#include <cuda_fp16.h>

__device__ __forceinline__ __half2 tanh_h2(__half2 v) {
    unsigned int uv, ur;
    memcpy(&uv, &v, 4);
    asm("tanh.approx.f16x2 %0, %1;" : "=r"(ur) : "r"(uv));
    __half2 r;
    memcpy(&r, &ur, 4);
    return r;
}
__device__ __forceinline__ float tanh_f32(float x) {
    float y;
    asm("tanh.approx.f32 %0, %1;" : "=f"(y) : "f"(x));
    return y;
}
// sigmoid(x) = 0.5 + 0.5*tanh(0.5*x) -> single MUFU, fp32 for final accuracy
__device__ __forceinline__ float sigmoid_fast(float x) {
    return fmaf(0.5f, tanh_f32(0.5f * x), 0.5f);
}

// Two pixels per thread-iteration, packed lane-wise into half2 (px0, px1).
// All matmuls HFMA2, hidden tanh f16x2, final sigmoid fp32.
// launch_bounds(128,4): regs capped at 128 (currently 121) -> 16 warps/SM.
__global__ void __launch_bounds__(128, 4)
mlp_field_kernel(const float4* __restrict__ x4,
                 const float* __restrict__ W_in,
                 const float* __restrict__ W_h,
                 const float* __restrict__ W_out,
                 float2* __restrict__ out2,
                 int npairs)
{
    // Duplicated-packed weights (w, w) as half2 — register resident,
    // amortized over the grid-stride loop.
    __half2 winx[8], winy[8];
#pragma unroll
    for (int j = 0; j < 8; j++) {
        winx[j] = __float2half2_rn(__ldg(W_in + 2 * j));
        winy[j] = __float2half2_rn(__ldg(W_in + 2 * j + 1));
    }
    __half2 wh[64];
#pragma unroll
    for (int i = 0; i < 64; i++) wh[i] = __float2half2_rn(__ldg(W_h + i));
    __half2 wout[24];
#pragma unroll
    for (int i = 0; i < 24; i++) wout[i] = __float2half2_rn(__ldg(W_out + i));

    const int stride = gridDim.x * blockDim.x;
    int p = blockIdx.x * blockDim.x + threadIdx.x;
    // pointer-increment addressing: no per-iteration IMAD on the fma pipe
    const float4* xp = x4 + p;
    float2* dst = out2 + 3ll * p;
    const long long xstep = stride;
    const long long dstep = 3ll * stride;

    for (; p < npairs; p += stride, xp += xstep, dst += dstep) {
        float4 xy = __ldg(xp);  // (x0, y0, x1, y1): two adjacent pixels

        // pack coords as (px0, px1)
        __half2 xv = __floats2half2_rn(xy.x, xy.z);
        __half2 yv = __floats2half2_rn(xy.y, xy.w);

        // ---- input layer ----
        __half2 h[8];
#pragma unroll
        for (int j = 0; j < 8; j++)
            h[j] = tanh_h2(__hfma2(winy[j], yv, __hmul2(winx[j], xv)));

        // ---- 4 shared-weight hidden layers, fully half2 ----
#pragma unroll
        for (int l = 0; l < 4; l++) {
            __half2 nh[8];
#pragma unroll
            for (int j = 0; j < 8; j++) {
                __half2 acc = __hmul2(wh[8 * j + 0], h[0]);
#pragma unroll
                for (int k = 1; k < 8; k++)
                    acc = __hfma2(wh[8 * j + k], h[k], acc);
                nh[j] = tanh_h2(acc);
            }
#pragma unroll
            for (int j = 0; j < 8; j++) h[j] = nh[j];
        }

        // ---- output layer in half2, sigmoid in fp32 ----
        float o0[3], o1[3];
#pragma unroll
        for (int o = 0; o < 3; o++) {
            __half2 acc = __hmul2(wout[8 * o + 0], h[0]);
#pragma unroll
            for (int k = 1; k < 8; k++)
                acc = __hfma2(wout[8 * o + k], h[k], acc);
            float2 a = __half22float2(acc);
            o0[o] = sigmoid_fast(a.x);
            o1[o] = sigmoid_fast(a.y);
        }

        // 6 contiguous floats per pair -> three 8B stores
        dst[0] = make_float2(o0[0], o0[1]);
        dst[1] = make_float2(o0[2], o1[0]);
        dst[2] = make_float2(o1[1], o1[2]);
    }
}

extern "C" void kernel_launch(void* const* d_in, const int* in_sizes, int n_in,
                              void* d_out, int out_size)
{
    const float* x     = (const float*)d_in[0];  // [N, 2]
    const float* W_in  = (const float*)d_in[1];  // [8, 2]
    const float* W_h   = (const float*)d_in[2];  // [8, 8]
    const float* W_out = (const float*)d_in[3];  // [3, 8]

    int n_pixels = in_sizes[0] / 2;
    int npairs = n_pixels / 2;  // N = 16777216, divisible by 4

    const int threads = 128;
    const int blocks = 608;  // exactly one resident wave: 152 SMs x 4 blocks
    mlp_field_kernel<<<blocks, threads>>>((const float4*)x, W_in, W_h, W_out,
                                          (float2*)d_out, npairs);
}

// round 5
// speedup vs baseline: 1.0022x; 1.0022x over previous
#include <cuda_runtime.h>
#include <cuda_fp16.h>

__device__ __forceinline__ __half2 tanh_h2(__half2 v) {
    unsigned int uv, ur;
    memcpy(&uv, &v, 4);
    asm("tanh.approx.f16x2 %0, %1;" : "=r"(ur) : "r"(uv));
    __half2 r;
    memcpy(&r, &ur, 4);
    return r;
}
__device__ __forceinline__ float tanh_f32(float x) {
    float y;
    asm("tanh.approx.f32 %0, %1;" : "=f"(y) : "f"(x));
    return y;
}
// sigmoid(x) = 0.5 + 0.5*tanh(0.5*x) -> single MUFU, fp32 for final accuracy
__device__ __forceinline__ float sigmoid_fast(float x) {
    return fmaf(0.5f, tanh_f32(0.5f * x), 0.5f);
}

// TWO independent pixel-pairs (4 pixels) per thread per iteration.
// Each pair is packed lane-wise into half2; the two pairs form two
// independent dependency chains -> 2x ILP to cover HFMA2/tanh latency.
__global__ void __launch_bounds__(128, 3)
mlp_field_kernel(const float4* __restrict__ x4,
                 const float* __restrict__ W_in,
                 const float* __restrict__ W_h,
                 const float* __restrict__ W_out,
                 float2* __restrict__ out2,
                 int npairs)
{
    // Duplicated-packed weights (w, w) as half2 — register resident.
    __half2 winx[8], winy[8];
#pragma unroll
    for (int j = 0; j < 8; j++) {
        winx[j] = __float2half2_rn(__ldg(W_in + 2 * j));
        winy[j] = __float2half2_rn(__ldg(W_in + 2 * j + 1));
    }
    __half2 wh[64];
#pragma unroll
    for (int i = 0; i < 64; i++) wh[i] = __float2half2_rn(__ldg(W_h + i));
    __half2 wout[24];
#pragma unroll
    for (int i = 0; i < 24; i++) wout[i] = __float2half2_rn(__ldg(W_out + i));

    const int nthreads = gridDim.x * blockDim.x;
    const int tidg = blockIdx.x * blockDim.x + threadIdx.x;
    // Pair indices: thread handles pairs (q) and (q + nthreads) each iter,
    // stepping by 2*nthreads. Both streams stay fully coalesced.
    const int step = 2 * nthreads;

    for (int q = tidg; q < npairs; q += step) {
        const int q2 = q + nthreads;
        const bool has2 = (q2 < npairs);

        float4 xyA = __ldg(x4 + q);
        float4 xyB = has2 ? __ldg(x4 + q2) : xyA;

        __half2 xvA = __floats2half2_rn(xyA.x, xyA.z);
        __half2 yvA = __floats2half2_rn(xyA.y, xyA.w);
        __half2 xvB = __floats2half2_rn(xyB.x, xyB.z);
        __half2 yvB = __floats2half2_rn(xyB.y, xyB.w);

        // ---- input layer, two interleaved streams ----
        __half2 hA[8], hB[8];
#pragma unroll
        for (int j = 0; j < 8; j++) {
            hA[j] = tanh_h2(__hfma2(winy[j], yvA, __hmul2(winx[j], xvA)));
            hB[j] = tanh_h2(__hfma2(winy[j], yvB, __hmul2(winx[j], xvB)));
        }

        // ---- 4 shared-weight hidden layers ----
#pragma unroll
        for (int l = 0; l < 4; l++) {
            __half2 nA[8], nB[8];
#pragma unroll
            for (int j = 0; j < 8; j++) {
                __half2 aA = __hmul2(wh[8 * j + 0], hA[0]);
                __half2 aB = __hmul2(wh[8 * j + 0], hB[0]);
#pragma unroll
                for (int k = 1; k < 8; k++) {
                    aA = __hfma2(wh[8 * j + k], hA[k], aA);
                    aB = __hfma2(wh[8 * j + k], hB[k], aB);
                }
                nA[j] = tanh_h2(aA);
                nB[j] = tanh_h2(aB);
            }
#pragma unroll
            for (int j = 0; j < 8; j++) { hA[j] = nA[j]; hB[j] = nB[j]; }
        }

        // ---- output layer + fp32 sigmoid ----
        float oA0[3], oA1[3], oB0[3], oB1[3];
#pragma unroll
        for (int o = 0; o < 3; o++) {
            __half2 aA = __hmul2(wout[8 * o + 0], hA[0]);
            __half2 aB = __hmul2(wout[8 * o + 0], hB[0]);
#pragma unroll
            for (int k = 1; k < 8; k++) {
                aA = __hfma2(wout[8 * o + k], hA[k], aA);
                aB = __hfma2(wout[8 * o + k], hB[k], aB);
            }
            float2 fA = __half22float2(aA);
            float2 fB = __half22float2(aB);
            oA0[o] = sigmoid_fast(fA.x);
            oA1[o] = sigmoid_fast(fA.y);
            oB0[o] = sigmoid_fast(fB.x);
            oB1[o] = sigmoid_fast(fB.y);
        }

        float2* dA = out2 + 3ll * q;
        dA[0] = make_float2(oA0[0], oA0[1]);
        dA[1] = make_float2(oA0[2], oA1[0]);
        dA[2] = make_float2(oA1[1], oA1[2]);
        if (has2) {
            float2* dB = out2 + 3ll * q2;
            dB[0] = make_float2(oB0[0], oB0[1]);
            dB[1] = make_float2(oB0[2], oB1[0]);
            dB[2] = make_float2(oB1[1], oB1[2]);
        }
    }
}

extern "C" void kernel_launch(void* const* d_in, const int* in_sizes, int n_in,
                              void* d_out, int out_size)
{
    const float* x     = (const float*)d_in[0];  // [N, 2]
    const float* W_in  = (const float*)d_in[1];  // [8, 2]
    const float* W_h   = (const float*)d_in[2];  // [8, 8]
    const float* W_out = (const float*)d_in[3];  // [3, 8]

    int n_pixels = in_sizes[0] / 2;
    int npairs = n_pixels / 2;  // N = 16777216, divisible by 4

    const int threads = 128;
    const int blocks = 912;  // fine-grained grid-stride: ~6 blocks/SM of work
    mlp_field_kernel<<<blocks, threads>>>((const float4*)x, W_in, W_h, W_out,
                                          (float2*)d_out, npairs);
}

// round 6
// speedup vs baseline: 1.0156x; 1.0134x over previous
#include <cuda_runtime.h>
#include <cuda_fp16.h>

__device__ __forceinline__ unsigned int h2u(__half2 h) {
    unsigned int u; memcpy(&u, &h, 4); return u;
}
__device__ __forceinline__ unsigned int tanh_h2u(unsigned int x) {
    unsigned int r;
    asm("tanh.approx.f16x2 %0, %1;" : "=r"(r) : "r"(x));
    return r;
}
__device__ __forceinline__ float tanh_f32(float x) {
    float y;
    asm("tanh.approx.f32 %0, %1;" : "=f"(y) : "f"(x));
    return y;
}
__device__ __forceinline__ float sigmoid_fast(float x) {
    return fmaf(0.5f, tanh_f32(0.5f * x), 0.5f);
}

// D[16,8] = A[16,8] * B[8,8] + C, all f16. D-frag layout == A-frag layout,
// so layers chain in registers with no data movement.
__device__ __forceinline__ void mma8_f16(unsigned int& d0, unsigned int& d1,
                                         unsigned int a0, unsigned int a1,
                                         unsigned int b) {
    unsigned int r0, r1;
    asm("mma.sync.aligned.m16n8k8.row.col.f16.f16.f16.f16 "
        "{%0,%1}, {%2,%3}, {%4}, {%5,%6};"
        : "=r"(r0), "=r"(r1)
        : "r"(a0), "r"(a1), "r"(b), "r"(0u), "r"(0u));
    d0 = r0; d1 = r1;
}
// Final layer with f32 accumulators for accurate sigmoid input.
__device__ __forceinline__ void mma8_f32(float& d0, float& d1, float& d2, float& d3,
                                         unsigned int a0, unsigned int a1,
                                         unsigned int b) {
    asm("mma.sync.aligned.m16n8k8.row.col.f32.f16.f16.f32 "
        "{%0,%1,%2,%3}, {%4,%5}, {%6}, {%7,%8,%9,%10};"
        : "=f"(d0), "=f"(d1), "=f"(d2), "=f"(d3)
        : "r"(a0), "r"(a1), "r"(b),
          "f"(0.0f), "f"(0.0f), "f"(0.0f), "f"(0.0f));
}

// One mma tile = 16 pixels. Each warp-iteration processes 4 independent tiles
// (64 pixels) for ILP. Weights live in 3 B-fragment registers total.
__global__ void __launch_bounds__(256)
mlp_mma_kernel(const float2* __restrict__ x2,
               const float* __restrict__ W_in,
               const float* __restrict__ W_h,
               const float* __restrict__ W_out,
               float* __restrict__ out,
               int ntiles)
{
    const int lane = threadIdx.x & 31;
    const int g = lane >> 2;   // group/row id 0..7
    const int c = lane & 3;    // col-pair id 0..3
    const int warp = (blockIdx.x * blockDim.x + threadIdx.x) >> 5;
    const int nwarps = (gridDim.x * blockDim.x) >> 5;

    // --- B fragments: b = {W[g][2c], W[g][2c+1]} (B[k,n] = W[n,k]) ---
    // Input layer: W_in is 8x2, k padded to 8 -> only c==0 lanes nonzero.
    unsigned int b_in = (c == 0)
        ? h2u(__floats2half2_rn(__ldg(W_in + 2 * g), __ldg(W_in + 2 * g + 1)))
        : 0u;
    // Hidden layer: W_h is 8x8 (shared across 4 layers).
    unsigned int b_h =
        h2u(__floats2half2_rn(__ldg(W_h + 8 * g + 2 * c), __ldg(W_h + 8 * g + 2 * c + 1)));
    // Output layer: W_out is 3x8, n padded to 8 -> rows g>=3 are zero.
    unsigned int b_out = (g < 3)
        ? h2u(__floats2half2_rn(__ldg(W_out + 8 * g + 2 * c), __ldg(W_out + 8 * g + 2 * c + 1)))
        : 0u;

    for (int t0 = warp * 4; t0 < ntiles; t0 += nwarps * 4) {
        unsigned int h0[4], h1[4];

        // ---- input layer: A[p,k] = (x,y,0,...) ----
#pragma unroll
        for (int u = 0; u < 4; u++) {
            int base = (t0 + u) * 16;
            // broadcast within each 4-lane group: address depends only on g
            float2 p0 = __ldg(x2 + base + g);
            float2 p1 = __ldg(x2 + base + 8 + g);
            unsigned int a0 = (c == 0) ? h2u(__floats2half2_rn(p0.x, p0.y)) : 0u;
            unsigned int a1 = (c == 0) ? h2u(__floats2half2_rn(p1.x, p1.y)) : 0u;
            unsigned int d0, d1;
            mma8_f16(d0, d1, a0, a1, b_in);
            h0[u] = tanh_h2u(d0);
            h1[u] = tanh_h2u(d1);
        }

        // ---- 4 shared-weight hidden layers ----
#pragma unroll
        for (int l = 0; l < 4; l++) {
#pragma unroll
            for (int u = 0; u < 4; u++) {
                unsigned int d0, d1;
                mma8_f16(d0, d1, h0[u], h1[u], b_h);
                h0[u] = tanh_h2u(d0);
                h1[u] = tanh_h2u(d1);
            }
        }

        // ---- output layer (f32 accum) + sigmoid + store ----
#pragma unroll
        for (int u = 0; u < 4; u++) {
            float d0, d1, d2, d3;
            mma8_f32(d0, d1, d2, d3, h0[u], h1[u], b_out);
            int base = (t0 + u) * 16;
            if (c < 2) {
                // c==0 owns cols 0,1 ; c==1 owns cols 2,(3=pad)
                float s0 = sigmoid_fast(d0);
                float s1 = sigmoid_fast(d1);
                float s2 = sigmoid_fast(d2);
                float s3 = sigmoid_fast(d3);
                int r0 = base + g;        // row g
                int r1 = base + 8 + g;    // row g+8
                if (c == 0) {
                    out[r0 * 3 + 0] = s0;
                    out[r0 * 3 + 1] = s1;
                    out[r1 * 3 + 0] = s2;
                    out[r1 * 3 + 1] = s3;
                } else {
                    out[r0 * 3 + 2] = s0;
                    out[r1 * 3 + 2] = s2;
                }
            }
        }
    }
}

extern "C" void kernel_launch(void* const* d_in, const int* in_sizes, int n_in,
                              void* d_out, int out_size)
{
    const float* x     = (const float*)d_in[0];  // [N, 2]
    const float* W_in  = (const float*)d_in[1];  // [8, 2]
    const float* W_h   = (const float*)d_in[2];  // [8, 8]
    const float* W_out = (const float*)d_in[3];  // [3, 8]

    int n_pixels = in_sizes[0] / 2;      // 16777216
    int ntiles = n_pixels / 16;          // 1048576, divisible by 4

    const int threads = 256;
    const int blocks = 1216;             // grid-stride; ~27 iters per warp
    mlp_mma_kernel<<<blocks, threads>>>((const float2*)x, W_in, W_h, W_out,
                                        (float*)d_out, ntiles);
}

// round 7
// speedup vs baseline: 1.0360x; 1.0201x over previous
#include <cuda_runtime.h>
#include <cuda_fp16.h>

__device__ __forceinline__ unsigned int h2u(__half2 h) {
    unsigned int u; memcpy(&u, &h, 4); return u;
}
__device__ __forceinline__ unsigned int tanh_h2u(unsigned int x) {
    unsigned int r;
    asm("tanh.approx.f16x2 %0, %1;" : "=r"(r) : "r"(x));
    return r;
}
__device__ __forceinline__ float tanh_f32(float x) {
    float y;
    asm("tanh.approx.f32 %0, %1;" : "=f"(y) : "f"(x));
    return y;
}
__device__ __forceinline__ float sigmoid_fast(float x) {
    return fmaf(0.5f, tanh_f32(0.5f * x), 0.5f);
}

// D[16,8] = A[16,8] * B[8,8] + 0, all f16. D-frag layout == A-frag layout,
// so layers chain in registers with no data movement.
__device__ __forceinline__ void mma8_f16(unsigned int& d0, unsigned int& d1,
                                         unsigned int a0, unsigned int a1,
                                         unsigned int b) {
    unsigned int r0, r1;
    asm("mma.sync.aligned.m16n8k8.row.col.f16.f16.f16.f16 "
        "{%0,%1}, {%2,%3}, {%4}, {%5,%6};"
        : "=r"(r0), "=r"(r1)
        : "r"(a0), "r"(a1), "r"(b), "r"(0u), "r"(0u));
    d0 = r0; d1 = r1;
}
// Final layer with f32 accumulators for accurate sigmoid input.
__device__ __forceinline__ void mma8_f32(float& d0, float& d1, float& d2, float& d3,
                                         unsigned int a0, unsigned int a1,
                                         unsigned int b) {
    asm("mma.sync.aligned.m16n8k8.row.col.f32.f16.f16.f32 "
        "{%0,%1,%2,%3}, {%4,%5}, {%6}, {%7,%8,%9,%10};"
        : "=f"(d0), "=f"(d1), "=f"(d2), "=f"(d3)
        : "r"(a0), "r"(a1), "r"(b),
          "f"(0.0f), "f"(0.0f), "f"(0.0f), "f"(0.0f));
}

#define ILP 8

// One mma tile = 16 pixels. Each warp-iteration processes ILP=8 independent
// tiles (128 pixels) -> 8 independent mma->tanh chains to cover latency.
// Weights live in 3 B-fragment registers total.
__global__ void __launch_bounds__(256)
mlp_mma_kernel(const float2* __restrict__ x2,
               const float* __restrict__ W_in,
               const float* __restrict__ W_h,
               const float* __restrict__ W_out,
               float* __restrict__ out,
               int ntiles)
{
    const int lane = threadIdx.x & 31;
    const int g = lane >> 2;   // group/row id 0..7
    const int c = lane & 3;    // col-pair id 0..3
    const int warp = (blockIdx.x * blockDim.x + threadIdx.x) >> 5;
    const int nwarps = (gridDim.x * blockDim.x) >> 5;

    // --- B fragments: b = {W[g][2c], W[g][2c+1]} (B[k,n] = W[n,k]) ---
    unsigned int b_in = (c == 0)
        ? h2u(__floats2half2_rn(__ldg(W_in + 2 * g), __ldg(W_in + 2 * g + 1)))
        : 0u;
    unsigned int b_h =
        h2u(__floats2half2_rn(__ldg(W_h + 8 * g + 2 * c), __ldg(W_h + 8 * g + 2 * c + 1)));
    unsigned int b_out = (g < 3)
        ? h2u(__floats2half2_rn(__ldg(W_out + 8 * g + 2 * c), __ldg(W_out + 8 * g + 2 * c + 1)))
        : 0u;

    for (int t0 = warp * ILP; t0 < ntiles; t0 += nwarps * ILP) {
        unsigned int h0[ILP], h1[ILP];

        // ---- input layer: A[p,k] = (x,y,0,...) ----
#pragma unroll
        for (int u = 0; u < ILP; u++) {
            int base = (t0 + u) * 16;
            float2 p0 = __ldg(x2 + base + g);       // broadcast in 4-lane group
            float2 p1 = __ldg(x2 + base + 8 + g);
            unsigned int a0 = (c == 0) ? h2u(__floats2half2_rn(p0.x, p0.y)) : 0u;
            unsigned int a1 = (c == 0) ? h2u(__floats2half2_rn(p1.x, p1.y)) : 0u;
            unsigned int d0, d1;
            mma8_f16(d0, d1, a0, a1, b_in);
            h0[u] = tanh_h2u(d0);
            h1[u] = tanh_h2u(d1);
        }

        // ---- 4 shared-weight hidden layers ----
#pragma unroll
        for (int l = 0; l < 4; l++) {
#pragma unroll
            for (int u = 0; u < ILP; u++) {
                unsigned int d0, d1;
                mma8_f16(d0, d1, h0[u], h1[u], b_h);
                h0[u] = tanh_h2u(d0);
                h1[u] = tanh_h2u(d1);
            }
        }

        // ---- output layer (f32 accum) + sigmoid + store ----
#pragma unroll
        for (int u = 0; u < ILP; u++) {
            float d0, d1, d2, d3;
            mma8_f32(d0, d1, d2, d3, h0[u], h1[u], b_out);
            int base = (t0 + u) * 16;
            if (c < 2) {
                float s0 = sigmoid_fast(d0);
                float s1 = sigmoid_fast(d1);
                float s2 = sigmoid_fast(d2);
                float s3 = sigmoid_fast(d3);
                int r0 = base + g;        // row g
                int r1 = base + 8 + g;    // row g+8
                if (c == 0) {
                    out[r0 * 3 + 0] = s0;
                    out[r0 * 3 + 1] = s1;
                    out[r1 * 3 + 0] = s2;
                    out[r1 * 3 + 1] = s3;
                } else {
                    out[r0 * 3 + 2] = s0;
                    out[r1 * 3 + 2] = s2;
                }
            }
        }
    }
}

extern "C" void kernel_launch(void* const* d_in, const int* in_sizes, int n_in,
                              void* d_out, int out_size)
{
    const float* x     = (const float*)d_in[0];  // [N, 2]
    const float* W_in  = (const float*)d_in[1];  // [8, 2]
    const float* W_h   = (const float*)d_in[2];  // [8, 8]
    const float* W_out = (const float*)d_in[3];  // [3, 8]

    int n_pixels = in_sizes[0] / 2;      // 16777216
    int ntiles = n_pixels / 16;          // 1048576, divisible by ILP=8

    const int threads = 256;
    const int blocks = 1216;             // grid-stride; ~13 iters per warp
    mlp_mma_kernel<<<blocks, threads>>>((const float2*)x, W_in, W_h, W_out,
                                        (float*)d_out, ntiles);
}